// round 1
// baseline (speedup 1.0000x reference)
#include <cuda_runtime.h>
#include <cuda_bf16.h>

// ---------------------------------------------------------------------------
// GaussianSelfAttention, separable-softmax formulation.
//   px[h,i,k] = softmax_k( a*mu1*(k-i) - a/2*(k-i)^2 )
//   py[h,j,l] = softmax_l( a*mu2*(l-j) - a/2*(l-j)^2 )
//   probs[i,j,h,k,l] = px[h,i,k]*py[h,j,l]
//   T[b,h,i,l,c]   = sum_k px[h,i,k] * hs[b,c,l,k]
//   vals[b,j,i,h*256+c] = sum_l py[h,j,l] * T[b,h,i,l,c]
//   out[b,o,j,i]   = sum_q vals[b,j,i,q] * value_w[o,q] + value_b[o]
// ---------------------------------------------------------------------------

#define S 48
#define CH 256
#define NH 9
#define BATCH 8
#define N2 2304              // 48*48, also NH*CH
#define OUT_ELEMS 4718592    // 8*256*48*48

typedef unsigned long long ull;

__device__ __align__(16) float g_px[NH * S * S];
__device__ __align__(16) float g_py[NH * S * S];
__device__ __align__(16) float g_T[BATCH * NH * S * S * CH];     // [b][h][i][l][c]
__device__ __align__(16) float g_vals[BATCH * S * S * N2];       // [b][j][i][q]
__device__ __align__(16) float g_Wt[N2 * CH];                    // [q][o]

__device__ __forceinline__ ull pack2(float lo, float hi) {
    ull r; asm("mov.b64 %0, {%1, %2};" : "=l"(r) : "f"(lo), "f"(hi)); return r;
}
__device__ __forceinline__ void unpack2(ull v, float& lo, float& hi) {
    asm("mov.b64 {%0, %1}, %2;" : "=f"(lo), "=f"(hi) : "l"(v));
}
__device__ __forceinline__ void fma2(ull& d, ull a, ull b) {
    asm("fma.rn.f32x2 %0, %1, %2, %0;" : "+l"(d) : "l"(a), "l"(b));
}

// ---------------------------------------------------------------------------
// 1) Per-head 1D softmax rows (tiny). t in [0, 2*9*48)
// ---------------------------------------------------------------------------
__global__ void k_axes(const float* __restrict__ centers,
                       const float* __restrict__ spreads) {
    int t = threadIdx.x;
    if (t >= 2 * NH * S) return;
    int which = t / (NH * S);
    int r = t - which * (NH * S);
    int h = r / S;
    int i = r - h * S;
    float sp = spreads[h];
    float a = sp * sp;
    float mu = centers[2 * h + which];
    float m = -1e30f;
    for (int k = 0; k < S; ++k) {
        float d = (float)(k - i);
        float s = a * mu * d - 0.5f * a * d * d;
        m = fmaxf(m, s);
    }
    float* dst = (which ? g_py : g_px) + h * (S * S) + i * S;
    float sum = 0.f;
    for (int k = 0; k < S; ++k) {
        float d = (float)(k - i);
        float s = a * mu * d - 0.5f * a * d * d;
        float e = expf(s - m);
        dst[k] = e;
        sum += e;
    }
    float inv = 1.0f / sum;
    for (int k = 0; k < S; ++k) dst[k] *= inv;
}

// ---------------------------------------------------------------------------
// 2) Transpose value_w (256 x 2304) -> Wt (2304 x 256)
// ---------------------------------------------------------------------------
__global__ void k_wt(const float* __restrict__ w) {
    int idx = blockIdx.x * 256 + threadIdx.x;
    if (idx < N2 * CH) {
        int o = idx / N2;
        int q = idx - o * N2;
        g_Wt[q * CH + o] = w[idx];
    }
}

// ---------------------------------------------------------------------------
// 3) probs[i,j,h,k,l] = px[h,i,k]*py[h,j,l]   (memory bound, 191 MB)
//    grid: 20736 blocks (i*432 + j*9 + h), block: 576 threads (k*12 + l/4)
// ---------------------------------------------------------------------------
__global__ void k_probs(float* __restrict__ out) {
    int bx = blockIdx.x;
    int i = bx / (S * NH);
    int rem = bx - i * (S * NH);
    int j = rem / NH;
    int h = rem - j * NH;
    int t = threadIdx.x;
    int k = t / 12;
    int lq = t - k * 12;
    float pxv = g_px[h * (S * S) + i * S + k];
    float4 pyv = *reinterpret_cast<const float4*>(g_py + h * (S * S) + j * S + lq * 4);
    float4 o;
    o.x = pxv * pyv.x; o.y = pxv * pyv.y; o.z = pxv * pyv.z; o.w = pxv * pyv.w;
    float* probs = out + OUT_ELEMS;
    int base = ((i * S + j) * NH + h) * N2 + k * S + lq * 4;
    *reinterpret_cast<float4*>(probs + base) = o;
}

// ---------------------------------------------------------------------------
// 4) Stage 1: T[b,h,i,l,c] = sum_k px[h,i,k] * hs[b,c,l,k]
//    grid: 8*48*2 = 768 blocks (b, l, c-half), block: 128 threads (one c each)
// ---------------------------------------------------------------------------
__global__ void __launch_bounds__(128) k_stage1(const float* __restrict__ hs) {
    __shared__ __align__(16) float xs[128 * 52];      // [c_local][k], pad 52
    __shared__ __align__(16) float pxs[S * S];
    int bx = blockIdx.x;
    int b = bx / 96;
    int r = bx - b * 96;
    int l = r >> 1;
    int ch = r & 1;
    int tid = threadIdx.x;
    int c = ch * 128 + tid;

    const float* src = hs + b * (CH * S * S) + (ch * 128) * (S * S) + l * S;
    for (int idx = tid; idx < 128 * S; idx += 128) {
        int cc = idx / S;
        int k = idx - cc * S;
        xs[cc * 52 + k] = src[cc * (S * S) + k];
    }
    const ull* xs2 = reinterpret_cast<const ull*>(xs + tid * 52);

    for (int h = 0; h < NH; ++h) {
        __syncthreads();
        for (int idx = tid; idx < S * S; idx += 128) pxs[idx] = g_px[h * (S * S) + idx];
        __syncthreads();
        float* Tbase = g_T + (((b * NH + h) * S) * S + l) * CH + c;
        for (int i0 = 0; i0 < S; i0 += 8) {
            ull acc[8];
            #pragma unroll
            for (int ii = 0; ii < 8; ++ii) acc[ii] = 0ull;
            #pragma unroll
            for (int k4 = 0; k4 < 12; ++k4) {
                ull xa = xs2[2 * k4];
                ull xb = xs2[2 * k4 + 1];
                #pragma unroll
                for (int ii = 0; ii < 8; ++ii) {
                    const ull* pr = reinterpret_cast<const ull*>(pxs + (i0 + ii) * S);
                    fma2(acc[ii], pr[2 * k4], xa);
                    fma2(acc[ii], pr[2 * k4 + 1], xb);
                }
            }
            #pragma unroll
            for (int ii = 0; ii < 8; ++ii) {
                float lo, hi;
                unpack2(acc[ii], lo, hi);
                Tbase[(i0 + ii) * (S * CH)] = lo + hi;
            }
        }
    }
}

// ---------------------------------------------------------------------------
// 5) Stage 2: vals[b,j,i,h*256+c] = sum_l py[h,j,l] * T[b,h,i,l,c]
//    grid: 768 blocks (b, i, c-half), block: 128 threads
// ---------------------------------------------------------------------------
__global__ void __launch_bounds__(128) k_stage2() {
    __shared__ float Ts[S * 129];                     // [l][c_local], pad 129
    __shared__ __align__(16) float pys[S * S];
    int bx = blockIdx.x;
    int b = bx / 96;
    int r = bx - b * 96;
    int i = r >> 1;
    int ch = r & 1;
    int tid = threadIdx.x;
    int c = ch * 128 + tid;

    for (int h = 0; h < NH; ++h) {
        __syncthreads();
        const float* Tsrc = g_T + ((b * NH + h) * S + i) * (S * CH) + ch * 128;
        for (int idx = tid; idx < S * 128; idx += 128) {
            int l = idx >> 7;
            int cc = idx & 127;
            Ts[l * 129 + cc] = Tsrc[l * CH + cc];
        }
        for (int idx = tid; idx < S * S; idx += 128) pys[idx] = g_py[h * (S * S) + idx];
        __syncthreads();
        float* vbase = g_vals + (b * N2 + i) * N2 + h * CH + c;   // + j*(48*2304)
        for (int j0 = 0; j0 < S; j0 += 8) {
            ull acc[8];
            #pragma unroll
            for (int jj = 0; jj < 8; ++jj) acc[jj] = 0ull;
            #pragma unroll
            for (int l4 = 0; l4 < 12; ++l4) {
                float t0 = Ts[(4 * l4 + 0) * 129 + tid];
                float t1 = Ts[(4 * l4 + 1) * 129 + tid];
                float t2 = Ts[(4 * l4 + 2) * 129 + tid];
                float t3 = Ts[(4 * l4 + 3) * 129 + tid];
                ull t01 = pack2(t0, t1);
                ull t23 = pack2(t2, t3);
                #pragma unroll
                for (int jj = 0; jj < 8; ++jj) {
                    const ull* pr = reinterpret_cast<const ull*>(pys + (j0 + jj) * S);
                    fma2(acc[jj], pr[2 * l4], t01);
                    fma2(acc[jj], pr[2 * l4 + 1], t23);
                }
            }
            #pragma unroll
            for (int jj = 0; jj < 8; ++jj) {
                float lo, hi;
                unpack2(acc[jj], lo, hi);
                vbase[(j0 + jj) * (S * N2)] = lo + hi;
            }
        }
    }
}

// ---------------------------------------------------------------------------
// 6) GEMM: out[b,o,j,i] = sum_q vals[m=(b,j,i)][q] * Wt[q][o] + bias[o]
//    M=18432, N=256, K=2304. BM=128, BN=128, BK=8, 256 threads, f32x2 FMA.
// ---------------------------------------------------------------------------
__global__ void __launch_bounds__(256, 2) k_gemm(const float* __restrict__ bias,
                                                 float* __restrict__ out) {
    __shared__ __align__(16) ull As2[8 * 128];        // [k][m], A value duplicated into pair
    __shared__ __align__(16) float Bs[8 * 128];       // [k][n]
    int tid = threadIdx.x;
    int m0 = blockIdx.x * 128;
    int n0 = blockIdx.y * 128;
    int tx = tid & 15;        // n-group: 8 outputs
    int ty = tid >> 4;        // m-group: 8 outputs
    int arow = tid >> 1;
    int acol = (tid & 1) * 4;
    int brow = tid >> 5;
    int bcol = (tid & 31) * 4;
    const float* Aptr = g_vals + (m0 + arow) * N2 + acol;
    const float* Bptr = g_Wt + brow * CH + n0 + bcol;

    ull acc[8][4];
    #pragma unroll
    for (int im = 0; im < 8; ++im)
        #pragma unroll
        for (int j = 0; j < 4; ++j) acc[im][j] = 0ull;

    for (int k0 = 0; k0 < N2; k0 += 8) {
        float4 av = *reinterpret_cast<const float4*>(Aptr + k0);
        float4 bv = *reinterpret_cast<const float4*>(Bptr + k0 * CH);
        __syncthreads();
        As2[(acol + 0) * 128 + arow] = pack2(av.x, av.x);
        As2[(acol + 1) * 128 + arow] = pack2(av.y, av.y);
        As2[(acol + 2) * 128 + arow] = pack2(av.z, av.z);
        As2[(acol + 3) * 128 + arow] = pack2(av.w, av.w);
        *reinterpret_cast<float4*>(Bs + brow * 128 + bcol) = bv;
        __syncthreads();
        #pragma unroll
        for (int kk = 0; kk < 8; ++kk) {
            ull a2[8];
            #pragma unroll
            for (int im = 0; im < 8; ++im) a2[im] = As2[kk * 128 + ty * 8 + im];
            const ull* b2p = reinterpret_cast<const ull*>(Bs + kk * 128 + tx * 8);
            ull b2[4];
            #pragma unroll
            for (int j = 0; j < 4; ++j) b2[j] = b2p[j];
            #pragma unroll
            for (int im = 0; im < 8; ++im)
                #pragma unroll
                for (int j = 0; j < 4; ++j) fma2(acc[im][j], a2[im], b2[j]);
        }
    }

    // Epilogue: out[b*589824 + n*2304 + (m - b*2304)], m contiguous per n.
    int b = m0 / N2;
    int mrel = m0 - b * N2 + ty * 8;
    float* obase = out + b * (CH * N2) + mrel;
    #pragma unroll
    for (int j = 0; j < 4; ++j) {
        float lo[8], hi[8];
        #pragma unroll
        for (int im = 0; im < 8; ++im) unpack2(acc[im][j], lo[im], hi[im]);
        int nlo = n0 + tx * 8 + 2 * j;
        float blo = bias[nlo];
        float bhi = bias[nlo + 1];
        float4 v;
        v = make_float4(lo[0] + blo, lo[1] + blo, lo[2] + blo, lo[3] + blo);
        *reinterpret_cast<float4*>(obase + nlo * N2) = v;
        v = make_float4(lo[4] + blo, lo[5] + blo, lo[6] + blo, lo[7] + blo);
        *reinterpret_cast<float4*>(obase + nlo * N2 + 4) = v;
        v = make_float4(hi[0] + bhi, hi[1] + bhi, hi[2] + bhi, hi[3] + bhi);
        *reinterpret_cast<float4*>(obase + (nlo + 1) * N2) = v;
        v = make_float4(hi[4] + bhi, hi[5] + bhi, hi[6] + bhi, hi[7] + bhi);
        *reinterpret_cast<float4*>(obase + (nlo + 1) * N2 + 4) = v;
    }
}

// ---------------------------------------------------------------------------
extern "C" void kernel_launch(void* const* d_in, const int* in_sizes, int n_in,
                              void* d_out, int out_size) {
    const float* hs      = (const float*)d_in[0];
    const float* centers = (const float*)d_in[1];
    const float* spreads = (const float*)d_in[2];
    const float* vw      = (const float*)d_in[3];
    const float* vb      = (const float*)d_in[4];
    float* out = (float*)d_out;

    k_axes<<<1, 864>>>(centers, spreads);
    k_wt<<<2304, 256>>>(vw);
    k_probs<<<20736, 576>>>(out);
    k_stage1<<<768, 128>>>(hs);
    k_stage2<<<768, 128>>>();
    k_gemm<<<dim3(144, 2), 256>>>(vb, out);
}

// round 3
// speedup vs baseline: 1.6166x; 1.6166x over previous
#include <cuda_runtime.h>
#include <cuda_bf16.h>
#include <cstdint>

// ---------------------------------------------------------------------------
// GaussianSelfAttention, separable-softmax formulation.
//   px[h,i,k] = softmax_k( a*mu1*(k-i) - a/2*(k-i)^2 )
//   py[h,j,l] = softmax_l( a*mu2*(l-j) - a/2*(l-j)^2 )
//   probs[i,j,h,k,l] = px[h,i,k]*py[h,j,l]
//   T[b,h,i,l,c]   = sum_k px[h,i,k] * hs[b,c,l,k]
//   vals[m=(b,j,i), q=(h,c)] = sum_l py[h,j,l] * T[b,h,i,l,c]  (bf16 hi/lo)
//   out[b,o,j,i]   = sum_q vals[m][q] * value_w[o][q] + value_b[o]  (HMMA)
// ---------------------------------------------------------------------------

#define S 48
#define CH 256
#define NH 9
#define BATCH 8
#define N2 2304              // 48*48, also NH*CH (= K of the GEMM)
#define MTOT 18432           // 8*48*48
#define OUT_ELEMS 4718592    // 8*256*48*48

typedef unsigned long long ull;

__device__ __align__(16) float g_px[NH * S * S];
__device__ __align__(16) float g_py[NH * S * S];
__device__ __align__(16) float g_T[BATCH * NH * S * S * CH];     // [b][h][i][l][c]
__device__ __align__(16) __nv_bfloat16 g_Ahi[(size_t)MTOT * N2]; // vals hi, [m][q]
__device__ __align__(16) __nv_bfloat16 g_Alo[(size_t)MTOT * N2]; // vals lo
__device__ __align__(16) __nv_bfloat16 g_Bhi[CH * N2];           // value_w hi, [o][q]
__device__ __align__(16) __nv_bfloat16 g_Blo[CH * N2];

__device__ __forceinline__ ull pack2(float lo, float hi) {
    ull r; asm("mov.b64 %0, {%1, %2};" : "=l"(r) : "f"(lo), "f"(hi)); return r;
}
__device__ __forceinline__ void unpack2(ull v, float& lo, float& hi) {
    asm("mov.b64 {%0, %1}, %2;" : "=f"(lo), "=f"(hi) : "l"(v));
}
__device__ __forceinline__ void fma2(ull& d, ull a, ull b) {
    asm("fma.rn.f32x2 %0, %1, %2, %0;" : "+l"(d) : "l"(a), "l"(b));
}
__device__ __forceinline__ uint32_t smem_u32(const void* p) {
    uint32_t a;
    asm("{ .reg .u64 t; cvta.to.shared.u64 t, %1; cvt.u32.u64 %0, t; }" : "=r"(a) : "l"(p));
    return a;
}

#define CP_ASYNC16(dst, src) \
    asm volatile("cp.async.cg.shared.global [%0], [%1], 16;" :: "r"(dst), "l"(src))
#define CP_COMMIT() asm volatile("cp.async.commit_group;" ::: "memory")

#define LDS32(x, addr) asm volatile("ld.shared.b32 %0, [%1];" : "=r"(x) : "r"(addr))

#define MMA16816(c, a, b0, b1) \
    asm volatile("mma.sync.aligned.m16n8k16.row.col.f32.bf16.bf16.f32 " \
                 "{%0,%1,%2,%3},{%4,%5,%6,%7},{%8,%9},{%0,%1,%2,%3};" \
                 : "+f"((c)[0]), "+f"((c)[1]), "+f"((c)[2]), "+f"((c)[3]) \
                 : "r"((a)[0]), "r"((a)[1]), "r"((a)[2]), "r"((a)[3]), \
                   "r"(b0), "r"(b1))

// ---------------------------------------------------------------------------
// 1) Per-head 1D softmax rows (tiny). t in [0, 2*9*48)
// ---------------------------------------------------------------------------
__global__ void k_axes(const float* __restrict__ centers,
                       const float* __restrict__ spreads) {
    int t = threadIdx.x;
    if (t >= 2 * NH * S) return;
    int which = t / (NH * S);
    int r = t - which * (NH * S);
    int h = r / S;
    int i = r - h * S;
    float sp = spreads[h];
    float a = sp * sp;
    float mu = centers[2 * h + which];
    float m = -1e30f;
    for (int k = 0; k < S; ++k) {
        float d = (float)(k - i);
        float s = a * mu * d - 0.5f * a * d * d;
        m = fmaxf(m, s);
    }
    float* dst = (which ? g_py : g_px) + h * (S * S) + i * S;
    float sum = 0.f;
    for (int k = 0; k < S; ++k) {
        float d = (float)(k - i);
        float s = a * mu * d - 0.5f * a * d * d;
        float e = expf(s - m);
        dst[k] = e;
        sum += e;
    }
    float inv = 1.0f / sum;
    for (int k = 0; k < S; ++k) dst[k] *= inv;
}

// ---------------------------------------------------------------------------
// 2) Convert value_w (fp32 [o][q]) -> bf16 hi/lo, same layout (K-major B)
// ---------------------------------------------------------------------------
__global__ void k_wconv(const float* __restrict__ w) {
    int idx = blockIdx.x * 256 + threadIdx.x;
    if (idx < CH * N2) {
        float v = w[idx];
        __nv_bfloat16 hi = __float2bfloat16(v);
        float lo = v - __bfloat162float(hi);
        g_Bhi[idx] = hi;
        g_Blo[idx] = __float2bfloat16(lo);
    }
}

// ---------------------------------------------------------------------------
// 3) probs[i,j,h,k,l] = px[h,i,k]*py[h,j,l]   (memory bound, 191 MB)
// ---------------------------------------------------------------------------
__global__ void k_probs(float* __restrict__ out) {
    int bx = blockIdx.x;
    int i = bx / (S * NH);
    int rem = bx - i * (S * NH);
    int j = rem / NH;
    int h = rem - j * NH;
    int t = threadIdx.x;
    int k = t / 12;
    int lq = t - k * 12;
    float pxv = g_px[h * (S * S) + i * S + k];
    float4 pyv = *reinterpret_cast<const float4*>(g_py + h * (S * S) + j * S + lq * 4);
    float4 o;
    o.x = pxv * pyv.x; o.y = pxv * pyv.y; o.z = pxv * pyv.z; o.w = pxv * pyv.w;
    float* probs = out + OUT_ELEMS;
    int base = ((i * S + j) * NH + h) * N2 + k * S + lq * 4;
    *reinterpret_cast<float4*>(probs + base) = o;
}

// ---------------------------------------------------------------------------
// 4) Stage 1: T[b,h,i,l,c] = sum_k px[h,i,k] * hs[b,c,l,k]
// ---------------------------------------------------------------------------
__global__ void __launch_bounds__(128) k_stage1(const float* __restrict__ hs) {
    __shared__ __align__(16) float xs[128 * 52];      // [c_local][k], pad 52
    __shared__ __align__(16) float pxs[S * S];
    int bx = blockIdx.x;
    int b = bx / 96;
    int r = bx - b * 96;
    int l = r >> 1;
    int ch = r & 1;
    int tid = threadIdx.x;
    int c = ch * 128 + tid;

    const float* src = hs + b * (CH * S * S) + (ch * 128) * (S * S) + l * S;
    for (int idx = tid; idx < 128 * S; idx += 128) {
        int cc = idx / S;
        int k = idx - cc * S;
        xs[cc * 52 + k] = src[cc * (S * S) + k];
    }
    const ull* xs2 = reinterpret_cast<const ull*>(xs + tid * 52);

    for (int h = 0; h < NH; ++h) {
        __syncthreads();
        for (int idx = tid; idx < S * S; idx += 128) pxs[idx] = g_px[h * (S * S) + idx];
        __syncthreads();
        float* Tbase = g_T + (((b * NH + h) * S) * S + l) * CH + c;
        for (int i0 = 0; i0 < S; i0 += 8) {
            ull acc[8];
            #pragma unroll
            for (int ii = 0; ii < 8; ++ii) acc[ii] = 0ull;
            #pragma unroll
            for (int k4 = 0; k4 < 12; ++k4) {
                ull xa = xs2[2 * k4];
                ull xb = xs2[2 * k4 + 1];
                #pragma unroll
                for (int ii = 0; ii < 8; ++ii) {
                    const ull* pr = reinterpret_cast<const ull*>(pxs + (i0 + ii) * S);
                    fma2(acc[ii], pr[2 * k4], xa);
                    fma2(acc[ii], pr[2 * k4 + 1], xb);
                }
            }
            #pragma unroll
            for (int ii = 0; ii < 8; ++ii) {
                float lo, hi;
                unpack2(acc[ii], lo, hi);
                Tbase[(i0 + ii) * (S * CH)] = lo + hi;
            }
        }
    }
}

// ---------------------------------------------------------------------------
// 5) Stage 2: vals[m=(b,j,i), q=(h,c)] = sum_l py[h,j,l] * T[b,h,i,l,c]
//    Writes bf16 hi/lo split directly (feeds the HMMA GEMM).
// ---------------------------------------------------------------------------
__global__ void __launch_bounds__(128) k_stage2() {
    __shared__ float Ts[S * 129];                     // [l][c_local], pad 129
    __shared__ __align__(16) float pys[S * S];
    int bx = blockIdx.x;
    int b = bx / 96;
    int r = bx - b * 96;
    int i = r >> 1;
    int ch = r & 1;
    int tid = threadIdx.x;
    int c = ch * 128 + tid;

    for (int h = 0; h < NH; ++h) {
        __syncthreads();
        const float* Tsrc = g_T + ((b * NH + h) * S + i) * (S * CH) + ch * 128;
        for (int idx = tid; idx < S * 128; idx += 128) {
            int l = idx >> 7;
            int cc = idx & 127;
            Ts[l * 129 + cc] = Tsrc[l * CH + cc];
        }
        for (int idx = tid; idx < S * S; idx += 128) pys[idx] = g_py[h * (S * S) + idx];
        __syncthreads();
        size_t vbase = (size_t)(b * N2 + i) * N2 + h * CH + c;    // + j*(48*2304)
        for (int j0 = 0; j0 < S; j0 += 8) {
            ull acc[8];
            #pragma unroll
            for (int jj = 0; jj < 8; ++jj) acc[jj] = 0ull;
            #pragma unroll
            for (int l4 = 0; l4 < 12; ++l4) {
                float t0 = Ts[(4 * l4 + 0) * 129 + tid];
                float t1 = Ts[(4 * l4 + 1) * 129 + tid];
                float t2 = Ts[(4 * l4 + 2) * 129 + tid];
                float t3 = Ts[(4 * l4 + 3) * 129 + tid];
                ull t01 = pack2(t0, t1);
                ull t23 = pack2(t2, t3);
                #pragma unroll
                for (int jj = 0; jj < 8; ++jj) {
                    const ull* pr = reinterpret_cast<const ull*>(pys + (j0 + jj) * S);
                    fma2(acc[jj], pr[2 * l4], t01);
                    fma2(acc[jj], pr[2 * l4 + 1], t23);
                }
            }
            #pragma unroll
            for (int jj = 0; jj < 8; ++jj) {
                float lo, hi;
                unpack2(acc[jj], lo, hi);
                float v = lo + hi;
                size_t idx = vbase + (size_t)(j0 + jj) * (S * N2);
                __nv_bfloat16 vh = __float2bfloat16(v);
                float rem = v - __bfloat162float(vh);
                g_Ahi[idx] = vh;
                g_Alo[idx] = __float2bfloat16(rem);
            }
        }
    }
}

// ---------------------------------------------------------------------------
// 6) HMMA GEMM: out[m][o] = sum_q vals[m][q]*W[o][q] + bias[o]
//    M=18432 (144 tiles), N=256 (2 tiles), K=2304 (144 k16 stages).
//    mma.sync m16n8k16 bf16->fp32; hi/lo split: D += Ahi*Bhi + Ahi*Blo + Alo*Bhi
//    SMEM row stride 48 B (16 bf16 + pad) -> conflict-free fragment LDS.
// ---------------------------------------------------------------------------
#define GST 6144                     // bytes per array per stage (128*48)
#define GSTAGE (4 * GST)             // Ahi,Alo,Bhi,Blo

__global__ void __launch_bounds__(256) k_gemm_mma(const float* __restrict__ bias,
                                                  float* __restrict__ out) {
    __shared__ __align__(16) char sm[2 * GSTAGE];    // 48 KB
    int tid = threadIdx.x;
    int wid = tid >> 5;
    int lane = tid & 31;
    int gq = lane >> 2;          // group row 0..7
    int tc = lane & 3;           // thread col 0..3
    int n0 = blockIdx.x * 128;   // N-blocks fastest -> A shared in L2
    int m0 = blockIdx.y * 128;
    int wm = (wid >> 1) * 32;
    int wn = (wid & 1) * 64;

    float c[2][8][4];
    #pragma unroll
    for (int mi = 0; mi < 2; ++mi)
        #pragma unroll
        for (int ni = 0; ni < 8; ++ni)
            #pragma unroll
            for (int r4 = 0; r4 < 4; ++r4) c[mi][ni][r4] = 0.f;

    // producer mapping: 256 threads -> 128 rows x 2 16B-chunks per array
    int pr = tid >> 1;
    int pc = tid & 1;
    const char* srcAhi = (const char*)g_Ahi + ((size_t)(m0 + pr) * N2) * 2 + pc * 16;
    const char* srcAlo = (const char*)g_Alo + ((size_t)(m0 + pr) * N2) * 2 + pc * 16;
    const char* srcBhi = (const char*)g_Bhi + ((size_t)(n0 + pr) * N2) * 2 + pc * 16;
    const char* srcBlo = (const char*)g_Blo + ((size_t)(n0 + pr) * N2) * 2 + pc * 16;
    uint32_t sbase = smem_u32(sm);
    uint32_t pdst = sbase + pr * 48 + pc * 16;

    // prologue: stage 0
    {
        CP_ASYNC16(pdst,               srcAhi);
        CP_ASYNC16(pdst + GST,         srcAlo);
        CP_ASYNC16(pdst + 2 * GST,     srcBhi);
        CP_ASYNC16(pdst + 3 * GST,     srcBlo);
        CP_COMMIT();
    }

    for (int s = 0; s < 144; ++s) {
        if (s + 1 < 144) {
            uint32_t d = pdst + ((s + 1) & 1) * GSTAGE;
            size_t koff = (size_t)(s + 1) * 32;       // 16 elems * 2B
            CP_ASYNC16(d,           srcAhi + koff);
            CP_ASYNC16(d + GST,     srcAlo + koff);
            CP_ASYNC16(d + 2 * GST, srcBhi + koff);
            CP_ASYNC16(d + 3 * GST, srcBlo + koff);
            CP_COMMIT();
            asm volatile("cp.async.wait_group 1;" ::: "memory");
        } else {
            asm volatile("cp.async.wait_group 0;" ::: "memory");
        }
        __syncthreads();

        uint32_t base = sbase + (s & 1) * GSTAGE;
        uint32_t ahi[2][4], alo[2][4];
        #pragma unroll
        for (int mi = 0; mi < 2; ++mi) {
            uint32_t ra = base + (wm + mi * 16 + gq) * 48 + tc * 4;
            LDS32(ahi[mi][0], ra);
            LDS32(ahi[mi][1], ra + 8 * 48);
            LDS32(ahi[mi][2], ra + 16);
            LDS32(ahi[mi][3], ra + 8 * 48 + 16);
            uint32_t rl = ra + GST;
            LDS32(alo[mi][0], rl);
            LDS32(alo[mi][1], rl + 8 * 48);
            LDS32(alo[mi][2], rl + 16);
            LDS32(alo[mi][3], rl + 8 * 48 + 16);
        }
        #pragma unroll
        for (int ni = 0; ni < 8; ++ni) {
            uint32_t nb = base + 2 * GST + (wn + ni * 8 + gq) * 48 + tc * 4;
            uint32_t bh0, bh1, bl0, bl1;
            LDS32(bh0, nb);
            LDS32(bh1, nb + 16);
            LDS32(bl0, nb + GST);
            LDS32(bl1, nb + GST + 16);
            #pragma unroll
            for (int mi = 0; mi < 2; ++mi) {
                MMA16816(c[mi][ni], ahi[mi], bh0, bh1);
                MMA16816(c[mi][ni], ahi[mi], bl0, bl1);
                MMA16816(c[mi][ni], alo[mi], bh0, bh1);
            }
        }
        __syncthreads();
    }

    // epilogue: out[b*CH*N2 + o*N2 + mrel], m contiguous
    int by = blockIdx.y;
    int b = by / 18;
    int mrel0 = (by - b * 18) * 128;
    float* ob = out + (size_t)b * (CH * N2) + mrel0;
    #pragma unroll
    for (int ni = 0; ni < 8; ++ni) {
        int o = n0 + wn + ni * 8 + tc * 2;
        float bv0 = __ldg(bias + o);
        float bv1 = __ldg(bias + o + 1);
        #pragma unroll
        for (int mi = 0; mi < 2; ++mi) {
            int m = wm + mi * 16 + gq;
            ob[(size_t)o * N2 + m]           = c[mi][ni][0] + bv0;
            ob[(size_t)(o + 1) * N2 + m]     = c[mi][ni][1] + bv1;
            ob[(size_t)o * N2 + m + 8]       = c[mi][ni][2] + bv0;
            ob[(size_t)(o + 1) * N2 + m + 8] = c[mi][ni][3] + bv1;
        }
    }
}

// ---------------------------------------------------------------------------
extern "C" void kernel_launch(void* const* d_in, const int* in_sizes, int n_in,
                              void* d_out, int out_size) {
    const float* hs      = (const float*)d_in[0];
    const float* centers = (const float*)d_in[1];
    const float* spreads = (const float*)d_in[2];
    const float* vw      = (const float*)d_in[3];
    const float* vb      = (const float*)d_in[4];
    float* out = (float*)d_out;

    k_axes<<<1, 864>>>(centers, spreads);
    k_wconv<<<2304, 256>>>(vw);
    k_probs<<<20736, 576>>>(out);
    k_stage1<<<768, 128>>>(hs);
    k_stage2<<<768, 128>>>();
    k_gemm_mma<<<dim3(2, 144), 256>>>(vb, out);
}

// round 4
// speedup vs baseline: 1.6895x; 1.0451x over previous
#include <cuda_runtime.h>
#include <cuda_bf16.h>
#include <cstdint>

// ---------------------------------------------------------------------------
// GaussianSelfAttention, separable-softmax formulation.
//   px[h,i,k] = softmax_k( a*mu1*(k-i) - a/2*(k-i)^2 )
//   py[h,j,l] = softmax_l( a*mu2*(l-j) - a/2*(l-j)^2 )
//   probs[i,j,h,k,l] = px[h,i,k]*py[h,j,l]
//   T[b,h,i,l,c]   = sum_k px[h,i,k] * hs[b,c,l,k]
//   vals[m=(b,j,i), q=(h,c)] = sum_l py[h,j,l] * T[b,h,i,l,c]  (bf16 hi/lo)
//   out[b,o,j,i]   = sum_q vals[m][q] * value_w[o][q] + value_b[o]  (HMMA)
// ---------------------------------------------------------------------------

#define S 48
#define CH 256
#define NH 9
#define BATCH 8
#define N2 2304              // 48*48, also NH*CH (= K of the GEMM)
#define MTOT 18432           // 8*48*48
#define OUT_ELEMS 4718592    // 8*256*48*48

typedef unsigned long long ull;

__device__ __align__(16) float g_px[NH * S * S];
__device__ __align__(16) float g_py[NH * S * S];
__device__ __align__(16) float g_T[BATCH * NH * S * S * CH];     // [b][h][i][l][c]
__device__ __align__(16) __nv_bfloat16 g_Ahi[(size_t)MTOT * N2]; // vals hi, [m][q]
__device__ __align__(16) __nv_bfloat16 g_Alo[(size_t)MTOT * N2]; // vals lo
__device__ __align__(16) __nv_bfloat16 g_Bhi[CH * N2];           // value_w hi, [o][q]
__device__ __align__(16) __nv_bfloat16 g_Blo[CH * N2];

__device__ __forceinline__ void unpack2(ull v, float& lo, float& hi) {
    asm("mov.b64 {%0, %1}, %2;" : "=f"(lo), "=f"(hi) : "l"(v));
}
__device__ __forceinline__ void fma2(ull& d, ull a, ull b) {
    asm("fma.rn.f32x2 %0, %1, %2, %0;" : "+l"(d) : "l"(a), "l"(b));
}
__device__ __forceinline__ uint32_t smem_u32(const void* p) {
    uint32_t a;
    asm("{ .reg .u64 t; cvta.to.shared.u64 t, %1; cvt.u32.u64 %0, t; }" : "=r"(a) : "l"(p));
    return a;
}

#define CP_ASYNC16(dst, src) \
    asm volatile("cp.async.cg.shared.global [%0], [%1], 16;" :: "r"(dst), "l"(src))
#define CP_COMMIT() asm volatile("cp.async.commit_group;" ::: "memory")

#define LDSM4(r0, r1, r2, r3, addr) \
    asm volatile("ldmatrix.sync.aligned.m8n8.x4.shared.b16 {%0,%1,%2,%3}, [%4];" \
                 : "=r"(r0), "=r"(r1), "=r"(r2), "=r"(r3) : "r"(addr))
#define LDSM2(r0, r1, addr) \
    asm volatile("ldmatrix.sync.aligned.m8n8.x2.shared.b16 {%0,%1}, [%2];" \
                 : "=r"(r0), "=r"(r1) : "r"(addr))

#define MMA16816(c, a, b0, b1) \
    asm volatile("mma.sync.aligned.m16n8k16.row.col.f32.bf16.bf16.f32 " \
                 "{%0,%1,%2,%3},{%4,%5,%6,%7},{%8,%9},{%0,%1,%2,%3};" \
                 : "+f"((c)[0]), "+f"((c)[1]), "+f"((c)[2]), "+f"((c)[3]) \
                 : "r"((a)[0]), "r"((a)[1]), "r"((a)[2]), "r"((a)[3]), \
                   "r"(b0), "r"(b1))

// ---------------------------------------------------------------------------
// 1) Per-head 1D softmax rows (tiny). t in [0, 2*9*48)
// ---------------------------------------------------------------------------
__global__ void k_axes(const float* __restrict__ centers,
                       const float* __restrict__ spreads) {
    int t = threadIdx.x;
    if (t >= 2 * NH * S) return;
    int which = t / (NH * S);
    int r = t - which * (NH * S);
    int h = r / S;
    int i = r - h * S;
    float sp = spreads[h];
    float a = sp * sp;
    float mu = centers[2 * h + which];
    float m = -1e30f;
    for (int k = 0; k < S; ++k) {
        float d = (float)(k - i);
        float s = a * mu * d - 0.5f * a * d * d;
        m = fmaxf(m, s);
    }
    float* dst = (which ? g_py : g_px) + h * (S * S) + i * S;
    float sum = 0.f;
    for (int k = 0; k < S; ++k) {
        float d = (float)(k - i);
        float s = a * mu * d - 0.5f * a * d * d;
        float e = expf(s - m);
        dst[k] = e;
        sum += e;
    }
    float inv = 1.0f / sum;
    for (int k = 0; k < S; ++k) dst[k] *= inv;
}

// ---------------------------------------------------------------------------
// 2) Convert value_w (fp32 [o][q]) -> bf16 hi/lo, same layout (K-major B)
// ---------------------------------------------------------------------------
__global__ void k_wconv(const float* __restrict__ w) {
    int idx = blockIdx.x * 256 + threadIdx.x;
    if (idx < CH * N2) {
        float v = w[idx];
        __nv_bfloat16 hi = __float2bfloat16(v);
        float lo = v - __bfloat162float(hi);
        g_Bhi[idx] = hi;
        g_Blo[idx] = __float2bfloat16(lo);
    }
}

// ---------------------------------------------------------------------------
// 3) probs[i,j,h,k,l] = px[h,i,k]*py[h,j,l]   (memory bound, 191 MB)
//    grid 2304 blocks (i,j), 256 threads
// ---------------------------------------------------------------------------
__global__ void __launch_bounds__(256) k_probs(float* __restrict__ out) {
    __shared__ __align__(16) float pxl[NH * S];
    __shared__ __align__(16) float pyl[NH * S];
    int i = blockIdx.x / S;
    int j = blockIdx.x - i * S;
    int tid = threadIdx.x;
    for (int t = tid; t < NH * S; t += 256) {
        int h = t / S;
        int k = t - h * S;
        pxl[t] = g_px[h * (S * S) + i * S + k];
        pyl[t] = g_py[h * (S * S) + j * S + k];
    }
    __syncthreads();
    float* probs = out + OUT_ELEMS + (size_t)(i * S + j) * NH * N2;
    for (int idx = tid; idx < NH * 576; idx += 256) {
        int h = idx / 576;
        int r = idx - h * 576;
        int k = r / 12;
        int lq = r - k * 12;
        float px = pxl[h * S + k];
        float4 py = *reinterpret_cast<const float4*>(pyl + h * S + lq * 4);
        float4 o;
        o.x = px * py.x; o.y = px * py.y; o.z = px * py.z; o.w = px * py.w;
        *reinterpret_cast<float4*>(probs + h * N2 + k * S + lq * 4) = o;
    }
}

// ---------------------------------------------------------------------------
// 4) Stage 1: T[b,h,i,l,c] = sum_k px[h,i,k] * hs[b,c,l,k]
//    grid 384 (b,l), 128 threads, 2 channels per thread, LDS128 everywhere.
// ---------------------------------------------------------------------------
#define SM_STAGE (256 * 52 * 4 + S * S * 4)   // 62464 bytes

__global__ void __launch_bounds__(128) k_stage1(const float* __restrict__ hs) {
    extern __shared__ __align__(16) float sm1[];
    float* xs  = sm1;              // [256][52]
    float* pxs = sm1 + 256 * 52;   // [48][48]
    int b = blockIdx.x / S;
    int l = blockIdx.x - b * S;
    int tid = threadIdx.x;

    const float* src = hs + (size_t)b * (CH * S * S) + l * S;
    for (int idx = tid; idx < 256 * S; idx += 128) {
        int cc = idx / S;
        int k = idx - cc * S;
        xs[cc * 52 + k] = src[cc * (S * S) + k];
    }
    const ulonglong2* xr0 = reinterpret_cast<const ulonglong2*>(xs + tid * 52);
    const ulonglong2* xr1 = reinterpret_cast<const ulonglong2*>(xs + (tid + 128) * 52);

    for (int h = 0; h < NH; ++h) {
        __syncthreads();
        for (int idx = tid; idx < S * S; idx += 128) pxs[idx] = g_px[h * (S * S) + idx];
        __syncthreads();
        float* Tb = g_T + ((size_t)((b * NH + h) * S) * S + l) * CH;
        for (int i0 = 0; i0 < S; i0 += 8) {
            ull a0[8], a1[8];
            #pragma unroll
            for (int ii = 0; ii < 8; ++ii) { a0[ii] = 0ull; a1[ii] = 0ull; }
            #pragma unroll
            for (int k4 = 0; k4 < 12; ++k4) {
                ulonglong2 x0 = xr0[k4];
                ulonglong2 x1 = xr1[k4];
                #pragma unroll
                for (int ii = 0; ii < 8; ++ii) {
                    ulonglong2 p = reinterpret_cast<const ulonglong2*>(pxs + (i0 + ii) * S)[k4];
                    fma2(a0[ii], p.x, x0.x); fma2(a0[ii], p.y, x0.y);
                    fma2(a1[ii], p.x, x1.x); fma2(a1[ii], p.y, x1.y);
                }
            }
            #pragma unroll
            for (int ii = 0; ii < 8; ++ii) {
                float lo, hi;
                unpack2(a0[ii], lo, hi);
                Tb[(size_t)(i0 + ii) * (S * CH) + tid] = lo + hi;
                unpack2(a1[ii], lo, hi);
                Tb[(size_t)(i0 + ii) * (S * CH) + tid + 128] = lo + hi;
            }
        }
    }
}

// ---------------------------------------------------------------------------
// 5) Stage 2: vals[m=(b,j,i), q=(h,c)] = sum_l py[h,j,l] * T[b,h,i,l,c]
//    grid 384 (b,i), 128 threads, T transposed in SMEM -> LDS128 reads.
//    Writes bf16 hi/lo split directly (feeds the HMMA GEMM).
// ---------------------------------------------------------------------------
__global__ void __launch_bounds__(128) k_stage2() {
    extern __shared__ __align__(16) float sm2[];
    float* TsT = sm2;              // [256 c][52 l]
    float* pys = sm2 + 256 * 52;   // [48][48]
    int b = blockIdx.x / S;
    int i = blockIdx.x - b * S;
    int tid = threadIdx.x;

    for (int h = 0; h < NH; ++h) {
        __syncthreads();
        const float* Tsrc = g_T + (size_t)((b * NH + h) * S + i) * (S * CH);
        for (int idx = tid; idx < S * CH; idx += 128) {
            int l = idx >> 8;
            int cc = idx & 255;
            TsT[cc * 52 + l] = Tsrc[idx];
        }
        for (int idx = tid; idx < S * S; idx += 128) pys[idx] = g_py[h * (S * S) + idx];
        __syncthreads();
        const ulonglong2* tr0 = reinterpret_cast<const ulonglong2*>(TsT + tid * 52);
        const ulonglong2* tr1 = reinterpret_cast<const ulonglong2*>(TsT + (tid + 128) * 52);
        size_t vb = (size_t)(b * N2 + i) * N2 + h * CH;
        for (int j0 = 0; j0 < S; j0 += 8) {
            ull a0[8], a1[8];
            #pragma unroll
            for (int jj = 0; jj < 8; ++jj) { a0[jj] = 0ull; a1[jj] = 0ull; }
            #pragma unroll
            for (int l4 = 0; l4 < 12; ++l4) {
                ulonglong2 t0 = tr0[l4];
                ulonglong2 t1 = tr1[l4];
                #pragma unroll
                for (int jj = 0; jj < 8; ++jj) {
                    ulonglong2 p = reinterpret_cast<const ulonglong2*>(pys + (j0 + jj) * S)[l4];
                    fma2(a0[jj], p.x, t0.x); fma2(a0[jj], p.y, t0.y);
                    fma2(a1[jj], p.x, t1.x); fma2(a1[jj], p.y, t1.y);
                }
            }
            #pragma unroll
            for (int jj = 0; jj < 8; ++jj) {
                float lo, hi;
                unpack2(a0[jj], lo, hi);
                float v0 = lo + hi;
                unpack2(a1[jj], lo, hi);
                float v1 = lo + hi;
                size_t m = vb + (size_t)(j0 + jj) * (S * N2);
                __nv_bfloat16 h0 = __float2bfloat16(v0);
                __nv_bfloat16 h1 = __float2bfloat16(v1);
                g_Ahi[m + tid] = h0;
                g_Ahi[m + tid + 128] = h1;
                g_Alo[m + tid] = __float2bfloat16(v0 - __bfloat162float(h0));
                g_Alo[m + tid + 128] = __float2bfloat16(v1 - __bfloat162float(h1));
            }
        }
    }
}

// ---------------------------------------------------------------------------
// 6) HMMA GEMM v2: out[m][o] = sum_q vals[m][q]*W[o][q] + bias[o]
//    BM=128, BN=128, BK=32, 72 stages, 3-buffer cp.async, ldmatrix loads.
//    hi/lo split: D += Ahi*Bhi + Ahi*Blo + Alo*Bhi
//    SMEM rows: 64 B data + 16 pad (stride 80) -> conflict-free LDSM.
// ---------------------------------------------------------------------------
#define GS_STRIDE 80
#define ARR_BYTES (128 * GS_STRIDE)      // 10240
#define STAGE_BYTES (4 * ARR_BYTES)      // 40960  (Ahi, Alo, Bhi, Blo)
#define KSTEPS 72                        // 2304 / 32
#define SMEM_GEMM (3 * STAGE_BYTES)      // 122880

#define GISSUE(s_) do { \
    uint32_t d_ = pd + ((s_) % 3) * STAGE_BYTES; \
    size_t ko_ = (size_t)(s_) * 64; \
    CP_ASYNC16(d_,                      gAh + ko_); \
    CP_ASYNC16(d_ + 16,                 gAh + ko_ + 16); \
    CP_ASYNC16(d_ + ARR_BYTES,          gAl + ko_); \
    CP_ASYNC16(d_ + ARR_BYTES + 16,     gAl + ko_ + 16); \
    CP_ASYNC16(d_ + 2 * ARR_BYTES,      gBh + ko_); \
    CP_ASYNC16(d_ + 2 * ARR_BYTES + 16, gBh + ko_ + 16); \
    CP_ASYNC16(d_ + 3 * ARR_BYTES,      gBl + ko_); \
    CP_ASYNC16(d_ + 3 * ARR_BYTES + 16, gBl + ko_ + 16); \
    CP_COMMIT(); \
} while (0)

__global__ void __launch_bounds__(256) k_gemm_mma(const float* __restrict__ bias,
                                                  float* __restrict__ out) {
    extern __shared__ __align__(16) char gsm[];
    uint32_t sb = smem_u32(gsm);
    int tid = threadIdx.x;
    int wid = tid >> 5;
    int lane = tid & 31;
    int gq = lane >> 2;
    int tc = lane & 3;
    int n0 = blockIdx.x * 128;
    int m0 = blockIdx.y * 128;
    int wm = (wid >> 1) * 32;
    int wn = (wid & 1) * 64;

    float c[2][8][4];
    #pragma unroll
    for (int mi = 0; mi < 2; ++mi)
        #pragma unroll
        for (int ni = 0; ni < 8; ++ni)
            #pragma unroll
            for (int r4 = 0; r4 < 4; ++r4) c[mi][ni][r4] = 0.f;

    // producer: thread -> row (tid>>1), 32B half (tid&1)
    int pr = tid >> 1;
    int ph = tid & 1;
    const char* gAh = (const char*)g_Ahi + ((size_t)(m0 + pr) * N2) * 2 + ph * 32;
    const char* gAl = (const char*)g_Alo + ((size_t)(m0 + pr) * N2) * 2 + ph * 32;
    const char* gBh = (const char*)g_Bhi + ((size_t)(n0 + pr) * N2) * 2 + ph * 32;
    const char* gBl = (const char*)g_Blo + ((size_t)(n0 + pr) * N2) * 2 + ph * 32;
    uint32_t pd = sb + pr * GS_STRIDE + ph * 32;

    // ldmatrix lane roles
    int arow = (lane & 7) + ((lane >> 3) & 1) * 8;   // row within m16 tile
    int achk = lane >> 4;                            // k8 chunk within k16
    int brow = lane & 7;
    int bchk = (lane >> 3) & 1;

    GISSUE(0);
    GISSUE(1);

    for (int s = 0; s < KSTEPS; ++s) {
        if (s) __syncthreads();                       // stage s-1 consumers done
        if (s + 2 < KSTEPS) {
            GISSUE(s + 2);
            asm volatile("cp.async.wait_group 2;" ::: "memory");
        } else if (s == KSTEPS - 2) {
            asm volatile("cp.async.wait_group 1;" ::: "memory");
        } else {
            asm volatile("cp.async.wait_group 0;" ::: "memory");
        }
        __syncthreads();

        uint32_t st = sb + (s % 3) * STAGE_BYTES;
        #pragma unroll
        for (int ks = 0; ks < 2; ++ks) {
            uint32_t ahi[2][4], alo[2][4];
            #pragma unroll
            for (int mi = 0; mi < 2; ++mi) {
                uint32_t aaddr = st + (wm + mi * 16 + arow) * GS_STRIDE + (ks * 2 + achk) * 16;
                LDSM4(ahi[mi][0], ahi[mi][1], ahi[mi][2], ahi[mi][3], aaddr);
                LDSM4(alo[mi][0], alo[mi][1], alo[mi][2], alo[mi][3], aaddr + ARR_BYTES);
            }
            #pragma unroll
            for (int nt = 0; nt < 8; ++nt) {
                uint32_t baddr = st + 2 * ARR_BYTES + (wn + nt * 8 + brow) * GS_STRIDE
                               + (ks * 2 + bchk) * 16;
                uint32_t bh0, bh1, bl0, bl1;
                LDSM2(bh0, bh1, baddr);
                LDSM2(bl0, bl1, baddr + ARR_BYTES);
                #pragma unroll
                for (int mi = 0; mi < 2; ++mi) {
                    MMA16816(c[mi][nt], ahi[mi], bh0, bh1);
                    MMA16816(c[mi][nt], ahi[mi], bl0, bl1);
                    MMA16816(c[mi][nt], alo[mi], bh0, bh1);
                }
            }
        }
    }

    // epilogue: out[b*CH*N2 + o*N2 + mrel], m contiguous
    int by = blockIdx.y;
    int b = by / 18;
    int mrel0 = (by - b * 18) * 128;
    float* ob = out + (size_t)b * (CH * N2) + mrel0;
    #pragma unroll
    for (int ni = 0; ni < 8; ++ni) {
        int o = n0 + wn + ni * 8 + tc * 2;
        float bv0 = __ldg(bias + o);
        float bv1 = __ldg(bias + o + 1);
        #pragma unroll
        for (int mi = 0; mi < 2; ++mi) {
            int m = wm + mi * 16 + gq;
            ob[(size_t)o * N2 + m]           = c[mi][ni][0] + bv0;
            ob[(size_t)(o + 1) * N2 + m]     = c[mi][ni][1] + bv1;
            ob[(size_t)o * N2 + m + 8]       = c[mi][ni][2] + bv0;
            ob[(size_t)(o + 1) * N2 + m + 8] = c[mi][ni][3] + bv1;
        }
    }
}

// ---------------------------------------------------------------------------
extern "C" void kernel_launch(void* const* d_in, const int* in_sizes, int n_in,
                              void* d_out, int out_size) {
    const float* hs      = (const float*)d_in[0];
    const float* centers = (const float*)d_in[1];
    const float* spreads = (const float*)d_in[2];
    const float* vw      = (const float*)d_in[3];
    const float* vb      = (const float*)d_in[4];
    float* out = (float*)d_out;

    cudaFuncSetAttribute(k_stage1, cudaFuncAttributeMaxDynamicSharedMemorySize, SM_STAGE);
    cudaFuncSetAttribute(k_stage2, cudaFuncAttributeMaxDynamicSharedMemorySize, SM_STAGE);
    cudaFuncSetAttribute(k_gemm_mma, cudaFuncAttributeMaxDynamicSharedMemorySize, SMEM_GEMM);

    k_axes<<<1, 864>>>(centers, spreads);
    k_wconv<<<2304, 256>>>(vw);
    k_probs<<<2304, 256>>>(out);
    k_stage1<<<384, 128, SM_STAGE>>>(hs);
    k_stage2<<<384, 128, SM_STAGE>>>();
    k_gemm_mma<<<dim3(2, 144), 256, SMEM_GEMM>>>(vb, out);
}

// round 7
// speedup vs baseline: 1.8376x; 1.0876x over previous
#include <cuda_runtime.h>
#include <cuda_bf16.h>
#include <cuda_fp16.h>
#include <cstdint>

// ---------------------------------------------------------------------------
// GaussianSelfAttention, separable-softmax formulation.
//   px[h,i,k] = softmax_k( a*mu1*(k-i) - a/2*(k-i)^2 )
//   py[h,j,l] = softmax_l( a*mu2*(l-j) - a/2*(l-j)^2 )
//   probs[i,j,h,k,l] = px[h,i,k]*py[h,j,l]
//   T[b,h,i,l,c]   = sum_k px[h,i,k] * hs[b,c,l,k]
//   vals[m=(b,j,i), q=(h,c)] = sum_l py[h,j,l] * T[b,h,i,l,c]  (fp16)
//   out[b,o,j,i]   = sum_q vals[m][q] * value_w[o][q] + value_b[o]
//                    (HMMA fp16, W split hi/lo, W scaled x256)
// ---------------------------------------------------------------------------

#define S 48
#define CH 256
#define NH 9
#define BATCH 8
#define N2 2304              // 48*48, also NH*CH (= K of the GEMM)
#define MTOT 18432           // 8*48*48
#define OUT_ELEMS 4718592    // 8*256*48*48

typedef unsigned long long ull;

__device__ __align__(16) float g_px[NH * S * S];
__device__ __align__(16) float g_py[NH * S * S];
__device__ __align__(16) float g_T[BATCH * NH * S * S * CH];     // [b][h][i][l][c]
__device__ __align__(16) __half g_Af[(size_t)MTOT * N2];         // vals fp16, [m][q]
__device__ __align__(16) __half g_Bh[CH * N2];                   // W*256 hi, [o][q]
__device__ __align__(16) __half g_Bl[CH * N2];                   // W*256 lo

__device__ __forceinline__ void unpack2(ull v, float& lo, float& hi) {
    asm("mov.b64 {%0, %1}, %2;" : "=f"(lo), "=f"(hi) : "l"(v));
}
__device__ __forceinline__ void fma2(ull& d, ull a, ull b) {
    asm("fma.rn.f32x2 %0, %1, %2, %0;" : "+l"(d) : "l"(a), "l"(b));
}
__device__ __forceinline__ uint32_t smem_u32(const void* p) {
    uint32_t a;
    asm("{ .reg .u64 t; cvta.to.shared.u64 t, %1; cvt.u32.u64 %0, t; }" : "=r"(a) : "l"(p));
    return a;
}

#define CP_ASYNC16(dst, src) \
    asm volatile("cp.async.cg.shared.global [%0], [%1], 16;" :: "r"(dst), "l"(src))
#define CP_COMMIT() asm volatile("cp.async.commit_group;" ::: "memory")

#define LDSM4(r0, r1, r2, r3, addr) \
    asm volatile("ldmatrix.sync.aligned.m8n8.x4.shared.b16 {%0,%1,%2,%3}, [%4];" \
                 : "=r"(r0), "=r"(r1), "=r"(r2), "=r"(r3) : "r"(addr))
#define LDSM2(r0, r1, addr) \
    asm volatile("ldmatrix.sync.aligned.m8n8.x2.shared.b16 {%0,%1}, [%2];" \
                 : "=r"(r0), "=r"(r1) : "r"(addr))

#define MMA16816H(c, a, b0, b1) \
    asm volatile("mma.sync.aligned.m16n8k16.row.col.f32.f16.f16.f32 " \
                 "{%0,%1,%2,%3},{%4,%5,%6,%7},{%8,%9},{%0,%1,%2,%3};" \
                 : "+f"((c)[0]), "+f"((c)[1]), "+f"((c)[2]), "+f"((c)[3]) \
                 : "r"((a)[0]), "r"((a)[1]), "r"((a)[2]), "r"((a)[3]), \
                   "r"(b0), "r"(b1))

// ---------------------------------------------------------------------------
// 1) Per-head 1D softmax rows (tiny). t in [0, 2*9*48)
// ---------------------------------------------------------------------------
__global__ void k_axes(const float* __restrict__ centers,
                       const float* __restrict__ spreads) {
    int t = threadIdx.x;
    if (t >= 2 * NH * S) return;
    int which = t / (NH * S);
    int r = t - which * (NH * S);
    int h = r / S;
    int i = r - h * S;
    float sp = spreads[h];
    float a = sp * sp;
    float mu = centers[2 * h + which];
    float m = -1e30f;
    for (int k = 0; k < S; ++k) {
        float d = (float)(k - i);
        float s = a * mu * d - 0.5f * a * d * d;
        m = fmaxf(m, s);
    }
    float* dst = (which ? g_py : g_px) + h * (S * S) + i * S;
    float sum = 0.f;
    for (int k = 0; k < S; ++k) {
        float d = (float)(k - i);
        float s = a * mu * d - 0.5f * a * d * d;
        float e = expf(s - m);
        dst[k] = e;
        sum += e;
    }
    float inv = 1.0f / sum;
    for (int k = 0; k < S; ++k) dst[k] *= inv;
}

// ---------------------------------------------------------------------------
// 2) Convert value_w (fp32 [o][q]) -> fp16 hi/lo of W*256 (K-major B)
// ---------------------------------------------------------------------------
__global__ void k_wconv(const float* __restrict__ w) {
    int idx = blockIdx.x * 256 + threadIdx.x;
    if (idx < CH * N2) {
        float v = w[idx] * 256.0f;
        __half hi = __float2half_rn(v);
        g_Bh[idx] = hi;
        g_Bl[idx] = __float2half_rn(v - __half2float(hi));
    }
}

// ---------------------------------------------------------------------------
// 3) probs[i,j,h,k,l] = px[h,i,k]*py[h,j,l]   (memory bound, 191 MB)
//    grid 2304 blocks (i,j), 256 threads
// ---------------------------------------------------------------------------
__global__ void __launch_bounds__(256) k_probs(float* __restrict__ out) {
    __shared__ __align__(16) float pxl[NH * S];
    __shared__ __align__(16) float pyl[NH * S];
    int i = blockIdx.x / S;
    int j = blockIdx.x - i * S;
    int tid = threadIdx.x;
    for (int t = tid; t < NH * S; t += 256) {
        int h = t / S;
        int k = t - h * S;
        pxl[t] = g_px[h * (S * S) + i * S + k];
        pyl[t] = g_py[h * (S * S) + j * S + k];
    }
    __syncthreads();
    float* probs = out + OUT_ELEMS + (size_t)(i * S + j) * NH * N2;
    for (int idx = tid; idx < NH * 576; idx += 256) {
        int h = idx / 576;
        int r = idx - h * 576;
        int k = r / 12;
        int lq = r - k * 12;
        float px = pxl[h * S + k];
        float4 py = *reinterpret_cast<const float4*>(pyl + h * S + lq * 4);
        float4 o;
        o.x = px * py.x; o.y = px * py.y; o.z = px * py.z; o.w = px * py.w;
        *reinterpret_cast<float4*>(probs + h * N2 + k * S + lq * 4) = o;
    }
}

// ---------------------------------------------------------------------------
// 4) Stage 1: T[b,h,i,l,c] = sum_k px[h,i,k] * hs[b,c,l,k]
//    grid 384 (b,l), 256 threads (one channel each), LDS128 everywhere.
// ---------------------------------------------------------------------------
#define SM_STAGE (256 * 52 * 4 + S * S * 4)   // 62464 bytes

__global__ void __launch_bounds__(256) k_stage1(const float* __restrict__ hs) {
    extern __shared__ __align__(16) float sm1[];
    float* xs  = sm1;              // [256][52]
    float* pxs = sm1 + 256 * 52;   // [48][48]
    int b = blockIdx.x / S;
    int l = blockIdx.x - b * S;
    int tid = threadIdx.x;

    const float* src = hs + (size_t)b * (CH * S * S) + l * S;
    for (int idx = tid; idx < 256 * S; idx += 256) {
        int cc = idx / S;
        int k = idx - cc * S;
        xs[cc * 52 + k] = src[cc * (S * S) + k];
    }
    const ulonglong2* xr = reinterpret_cast<const ulonglong2*>(xs + tid * 52);

    for (int h = 0; h < NH; ++h) {
        __syncthreads();
        for (int idx = tid; idx < S * S; idx += 256) pxs[idx] = g_px[h * (S * S) + idx];
        __syncthreads();
        float* Tb = g_T + ((size_t)((b * NH + h) * S) * S + l) * CH + tid;
        for (int i0 = 0; i0 < S; i0 += 8) {
            ull a0[8];
            #pragma unroll
            for (int ii = 0; ii < 8; ++ii) a0[ii] = 0ull;
            #pragma unroll
            for (int k4 = 0; k4 < 12; ++k4) {
                ulonglong2 x = xr[k4];
                #pragma unroll
                for (int ii = 0; ii < 8; ++ii) {
                    ulonglong2 p = reinterpret_cast<const ulonglong2*>(pxs + (i0 + ii) * S)[k4];
                    fma2(a0[ii], p.x, x.x);
                    fma2(a0[ii], p.y, x.y);
                }
            }
            #pragma unroll
            for (int ii = 0; ii < 8; ++ii) {
                float lo, hi;
                unpack2(a0[ii], lo, hi);
                Tb[(size_t)(i0 + ii) * (S * CH)] = lo + hi;
            }
        }
    }
}

// ---------------------------------------------------------------------------
// 5) Stage 2: vals[m=(b,j,i), q=(h,c)] = sum_l py[h,j,l] * T[b,h,i,l,c]
//    grid 384 (b,i), 256 threads, T transposed in SMEM with chunk swizzle
//    (conflict-free STS + LDS128). tr[l4^swz] holds LOGICAL chunk l4, so the
//    matching py chunk is [l4] (warp-uniform broadcast).
//    Writes fp16 directly (feeds HMMA GEMM).
// ---------------------------------------------------------------------------
__global__ void __launch_bounds__(256) k_stage2() {
    extern __shared__ __align__(16) float sm2[];
    float* TsT = sm2;              // [256 c][52 l], 16B-chunk swizzled
    float* pys = sm2 + 256 * 52;   // [48][48]
    int b = blockIdx.x / S;
    int i = blockIdx.x - b * S;
    int tid = threadIdx.x;
    int swz = (tid >> 3) & 3;

    for (int h = 0; h < NH; ++h) {
        __syncthreads();
        const float* Tsrc = g_T + (size_t)((b * NH + h) * S + i) * (S * CH);
        for (int idx = tid; idx < S * CH; idx += 256) {
            int l = idx >> 8;
            int cc = idx & 255;
            int chunk = (l >> 2) ^ ((cc >> 3) & 3);
            TsT[cc * 52 + chunk * 4 + (l & 3)] = Tsrc[idx];
        }
        for (int idx = tid; idx < S * S; idx += 256) pys[idx] = g_py[h * (S * S) + idx];
        __syncthreads();
        const ulonglong2* tr = reinterpret_cast<const ulonglong2*>(TsT + tid * 52);
        size_t vb = (size_t)(b * N2 + i) * N2 + h * CH + tid;
        for (int j0 = 0; j0 < S; j0 += 8) {
            ull a0[8];
            #pragma unroll
            for (int jj = 0; jj < 8; ++jj) a0[jj] = 0ull;
            #pragma unroll
            for (int l4 = 0; l4 < 12; ++l4) {
                ulonglong2 t = tr[l4 ^ swz];     // physical chunk holding logical l4
                #pragma unroll
                for (int jj = 0; jj < 8; ++jj) {
                    ulonglong2 p = reinterpret_cast<const ulonglong2*>(pys + (j0 + jj) * S)[l4];
                    fma2(a0[jj], p.x, t.x);
                    fma2(a0[jj], p.y, t.y);
                }
            }
            #pragma unroll
            for (int jj = 0; jj < 8; ++jj) {
                float lo, hi;
                unpack2(a0[jj], lo, hi);
                g_Af[vb + (size_t)(j0 + jj) * (S * N2)] = __float2half_rn(lo + hi);
            }
        }
    }
}

// ---------------------------------------------------------------------------
// 6) HMMA GEMM: out[m][o] = (sum_q A[m][q]*W256[o][q])/256 + bias[o]
//    BM=128, BN=128, BK=32, 72 stages, 3-buffer cp.async, ldmatrix loads.
//    fp16 split-B: D += A*Bhi + A*Blo   (A single fp16)
//    SMEM rows: 64 B data + 16 pad (stride 80) -> conflict-free LDSM.
// ---------------------------------------------------------------------------
#define GS_STRIDE 80
#define ARR_BYTES (128 * GS_STRIDE)      // 10240
#define STAGE_BYTES (3 * ARR_BYTES)      // 30720  (A, Bhi, Blo)
#define KSTEPS 72                        // 2304 / 32
#define SMEM_GEMM (3 * STAGE_BYTES)      // 92160

#define GISSUE(s_) do { \
    uint32_t d_ = pd + ((s_) % 3) * STAGE_BYTES; \
    size_t ko_ = (size_t)(s_) * 64; \
    CP_ASYNC16(d_,                      gA  + ko_); \
    CP_ASYNC16(d_ + 16,                 gA  + ko_ + 16); \
    CP_ASYNC16(d_ + ARR_BYTES,          gBh + ko_); \
    CP_ASYNC16(d_ + ARR_BYTES + 16,     gBh + ko_ + 16); \
    CP_ASYNC16(d_ + 2 * ARR_BYTES,      gBl + ko_); \
    CP_ASYNC16(d_ + 2 * ARR_BYTES + 16, gBl + ko_ + 16); \
    CP_COMMIT(); \
} while (0)

__global__ void __launch_bounds__(256) k_gemm_mma(const float* __restrict__ bias,
                                                  float* __restrict__ out) {
    extern __shared__ __align__(16) char gsm[];
    uint32_t sb = smem_u32(gsm);
    int tid = threadIdx.x;
    int wid = tid >> 5;
    int lane = tid & 31;
    int gq = lane >> 2;
    int tc = lane & 3;
    int n0 = blockIdx.x * 128;
    int m0 = blockIdx.y * 128;
    int wm = (wid >> 1) * 32;
    int wn = (wid & 1) * 64;

    float c[2][8][4];
    #pragma unroll
    for (int mi = 0; mi < 2; ++mi)
        #pragma unroll
        for (int ni = 0; ni < 8; ++ni)
            #pragma unroll
            for (int r4 = 0; r4 < 4; ++r4) c[mi][ni][r4] = 0.f;

    // producer: thread -> row (tid>>1), 32B half (tid&1)
    int pr = tid >> 1;
    int ph = tid & 1;
    const char* gA  = (const char*)g_Af + ((size_t)(m0 + pr) * N2) * 2 + ph * 32;
    const char* gBh = (const char*)g_Bh + ((size_t)(n0 + pr) * N2) * 2 + ph * 32;
    const char* gBl = (const char*)g_Bl + ((size_t)(n0 + pr) * N2) * 2 + ph * 32;
    uint32_t pd = sb + pr * GS_STRIDE + ph * 32;

    // ldmatrix lane roles
    int arow = (lane & 7) + ((lane >> 3) & 1) * 8;   // row within m16 tile
    int achk = lane >> 4;                            // k8 chunk within k16
    int brow = lane & 7;
    int bchk = (lane >> 3) & 1;

    GISSUE(0);
    GISSUE(1);

    for (int s = 0; s < KSTEPS; ++s) {
        if (s) __syncthreads();                       // stage s-1 consumers done
        if (s + 2 < KSTEPS) {
            GISSUE(s + 2);
            asm volatile("cp.async.wait_group 2;" ::: "memory");
        } else if (s == KSTEPS - 2) {
            asm volatile("cp.async.wait_group 1;" ::: "memory");
        } else {
            asm volatile("cp.async.wait_group 0;" ::: "memory");
        }
        __syncthreads();

        uint32_t st = sb + (s % 3) * STAGE_BYTES;
        #pragma unroll
        for (int ks = 0; ks < 2; ++ks) {
            uint32_t a[2][4];
            #pragma unroll
            for (int mi = 0; mi < 2; ++mi) {
                uint32_t aaddr = st + (wm + mi * 16 + arow) * GS_STRIDE + (ks * 2 + achk) * 16;
                LDSM4(a[mi][0], a[mi][1], a[mi][2], a[mi][3], aaddr);
            }
            #pragma unroll
            for (int nt = 0; nt < 8; ++nt) {
                uint32_t baddr = st + ARR_BYTES + (wn + nt * 8 + brow) * GS_STRIDE
                               + (ks * 2 + bchk) * 16;
                uint32_t bh0, bh1, bl0, bl1;
                LDSM2(bh0, bh1, baddr);
                LDSM2(bl0, bl1, baddr + ARR_BYTES);
                #pragma unroll
                for (int mi = 0; mi < 2; ++mi) {
                    MMA16816H(c[mi][nt], a[mi], bh0, bh1);
                    MMA16816H(c[mi][nt], a[mi], bl0, bl1);
                }
            }
        }
    }

    // epilogue: out[b*CH*N2 + o*N2 + mrel], m contiguous; undo x256 W scale
    const float inv = 1.0f / 256.0f;
    int by = blockIdx.y;
    int b = by / 18;
    int mrel0 = (by - b * 18) * 128;
    float* ob = out + (size_t)b * (CH * N2) + mrel0;
    #pragma unroll
    for (int ni = 0; ni < 8; ++ni) {
        int o = n0 + wn + ni * 8 + tc * 2;
        float bv0 = __ldg(bias + o);
        float bv1 = __ldg(bias + o + 1);
        #pragma unroll
        for (int mi = 0; mi < 2; ++mi) {
            int m = wm + mi * 16 + gq;
            ob[(size_t)o * N2 + m]           = c[mi][ni][0] * inv + bv0;
            ob[(size_t)(o + 1) * N2 + m]     = c[mi][ni][1] * inv + bv1;
            ob[(size_t)o * N2 + m + 8]       = c[mi][ni][2] * inv + bv0;
            ob[(size_t)(o + 1) * N2 + m + 8] = c[mi][ni][3] * inv + bv1;
        }
    }
}

// ---------------------------------------------------------------------------
extern "C" void kernel_launch(void* const* d_in, const int* in_sizes, int n_in,
                              void* d_out, int out_size) {
    const float* hs      = (const float*)d_in[0];
    const float* centers = (const float*)d_in[1];
    const float* spreads = (const float*)d_in[2];
    const float* vw      = (const float*)d_in[3];
    const float* vb      = (const float*)d_in[4];
    float* out = (float*)d_out;

    cudaFuncSetAttribute(k_stage1, cudaFuncAttributeMaxDynamicSharedMemorySize, SM_STAGE);
    cudaFuncSetAttribute(k_stage2, cudaFuncAttributeMaxDynamicSharedMemorySize, SM_STAGE);
    cudaFuncSetAttribute(k_gemm_mma, cudaFuncAttributeMaxDynamicSharedMemorySize, SMEM_GEMM);

    k_axes<<<1, 864>>>(centers, spreads);
    k_wconv<<<2304, 256>>>(vw);
    k_probs<<<2304, 256>>>(out);
    k_stage1<<<384, 256, SM_STAGE>>>(hs);
    k_stage2<<<384, 256, SM_STAGE>>>();
    k_gemm_mma<<<dim3(2, 144), 256, SMEM_GEMM>>>(vb, out);
}

// round 8
// speedup vs baseline: 2.0875x; 1.1360x over previous
#include <cuda_runtime.h>
#include <cuda_bf16.h>
#include <cuda_fp16.h>
#include <cstdint>

// ---------------------------------------------------------------------------
// GaussianSelfAttention, separable-softmax formulation.
//   px[h,i,k] = softmax_k( a*mu1*(k-i) - a/2*(k-i)^2 )
//   py[h,j,l] = softmax_l( a*mu2*(l-j) - a/2*(l-j)^2 )
//   probs[i,j,h,k,l] = px[h,i,k]*py[h,j,l]
//   T[b,h,i,l,c]   = sum_k px[h,i,k] * hs[b,c,l,k]
//   vals[m=(b,j,i), q=(h,c)] = sum_l py[h,j,l] * T[b,h,i,l,c]  (fp16)
//   out[b,o,j,i]   = sum_q vals[m][q] * value_w[o][q] + value_b[o]
//                    (HMMA fp16, W split hi/lo, W scaled x256)
// ---------------------------------------------------------------------------

#define S 48
#define CH 256
#define NH 9
#define BATCH 8
#define N2 2304              // 48*48, also NH*CH (= K of the GEMM)
#define MTOT 18432           // 8*48*48
#define OUT_ELEMS 4718592    // 8*256*48*48

typedef unsigned long long ull;

__device__ __align__(16) float g_px[NH * S * S];
__device__ __align__(16) float g_py[NH * S * S];
__device__ __align__(16) float g_T[BATCH * NH * S * S * CH];     // [b][h][i][l][c]
__device__ __align__(16) __half g_Af[(size_t)MTOT * N2];         // vals fp16, [m][q]
__device__ __align__(16) __half g_Bh[CH * N2];                   // W*256 hi, [o][q]
__device__ __align__(16) __half g_Bl[CH * N2];                   // W*256 lo

__device__ __forceinline__ ull pack2(float lo, float hi) {
    ull r; asm("mov.b64 %0, {%1, %2};" : "=l"(r) : "f"(lo), "f"(hi)); return r;
}
__device__ __forceinline__ void unpack2(ull v, float& lo, float& hi) {
    asm("mov.b64 {%0, %1}, %2;" : "=f"(lo), "=f"(hi) : "l"(v));
}
__device__ __forceinline__ void fma2(ull& d, ull a, ull b) {
    asm("fma.rn.f32x2 %0, %1, %2, %0;" : "+l"(d) : "l"(a), "l"(b));
}
__device__ __forceinline__ uint32_t smem_u32(const void* p) {
    uint32_t a;
    asm("{ .reg .u64 t; cvta.to.shared.u64 t, %1; cvt.u32.u64 %0, t; }" : "=r"(a) : "l"(p));
    return a;
}

#define CP_ASYNC16(dst, src) \
    asm volatile("cp.async.cg.shared.global [%0], [%1], 16;" :: "r"(dst), "l"(src))
#define CP_COMMIT() asm volatile("cp.async.commit_group;" ::: "memory")

#define LDSM4(r0, r1, r2, r3, addr) \
    asm volatile("ldmatrix.sync.aligned.m8n8.x4.shared.b16 {%0,%1,%2,%3}, [%4];" \
                 : "=r"(r0), "=r"(r1), "=r"(r2), "=r"(r3) : "r"(addr))
#define LDSM2(r0, r1, addr) \
    asm volatile("ldmatrix.sync.aligned.m8n8.x2.shared.b16 {%0,%1}, [%2];" \
                 : "=r"(r0), "=r"(r1) : "r"(addr))

#define MMA16816H(c, a, b0, b1) \
    asm volatile("mma.sync.aligned.m16n8k16.row.col.f32.f16.f16.f32 " \
                 "{%0,%1,%2,%3},{%4,%5,%6,%7},{%8,%9},{%0,%1,%2,%3};" \
                 : "+f"((c)[0]), "+f"((c)[1]), "+f"((c)[2]), "+f"((c)[3]) \
                 : "r"((a)[0]), "r"((a)[1]), "r"((a)[2]), "r"((a)[3]), \
                   "r"(b0), "r"(b1))

// ---------------------------------------------------------------------------
// 1) Per-head 1D softmax rows (tiny). t in [0, 2*9*48)
// ---------------------------------------------------------------------------
__global__ void k_axes(const float* __restrict__ centers,
                       const float* __restrict__ spreads) {
    int t = threadIdx.x;
    if (t >= 2 * NH * S) return;
    int which = t / (NH * S);
    int r = t - which * (NH * S);
    int h = r / S;
    int i = r - h * S;
    float sp = spreads[h];
    float a = sp * sp;
    float mu = centers[2 * h + which];
    float m = -1e30f;
    for (int k = 0; k < S; ++k) {
        float d = (float)(k - i);
        float s = a * mu * d - 0.5f * a * d * d;
        m = fmaxf(m, s);
    }
    float* dst = (which ? g_py : g_px) + h * (S * S) + i * S;
    float sum = 0.f;
    for (int k = 0; k < S; ++k) {
        float d = (float)(k - i);
        float s = a * mu * d - 0.5f * a * d * d;
        float e = expf(s - m);
        dst[k] = e;
        sum += e;
    }
    float inv = 1.0f / sum;
    for (int k = 0; k < S; ++k) dst[k] *= inv;
}

// ---------------------------------------------------------------------------
// 2) Convert value_w (fp32 [o][q]) -> fp16 hi/lo of W*256 (K-major B)
// ---------------------------------------------------------------------------
__global__ void k_wconv(const float* __restrict__ w) {
    int idx = blockIdx.x * 256 + threadIdx.x;
    if (idx < CH * N2) {
        float v = w[idx] * 256.0f;
        __half hi = __float2half_rn(v);
        g_Bh[idx] = hi;
        g_Bl[idx] = __float2half_rn(v - __half2float(hi));
    }
}

// ---------------------------------------------------------------------------
// 3) probs[i,j,h,k,l] = px[h,i,k]*py[h,j,l]   (memory bound, 191 MB)
//    grid 2304 blocks (i,j), 256 threads
// ---------------------------------------------------------------------------
__global__ void __launch_bounds__(256) k_probs(float* __restrict__ out) {
    __shared__ __align__(16) float pxl[NH * S];
    __shared__ __align__(16) float pyl[NH * S];
    int i = blockIdx.x / S;
    int j = blockIdx.x - i * S;
    int tid = threadIdx.x;
    for (int t = tid; t < NH * S; t += 256) {
        int h = t / S;
        int k = t - h * S;
        pxl[t] = g_px[h * (S * S) + i * S + k];
        pyl[t] = g_py[h * (S * S) + j * S + k];
    }
    __syncthreads();
    float* probs = out + OUT_ELEMS + (size_t)(i * S + j) * NH * N2;
    for (int idx = tid; idx < NH * 576; idx += 256) {
        int h = idx / 576;
        int r = idx - h * 576;
        int k = r / 12;
        int lq = r - k * 12;
        float px = pxl[h * S + k];
        float4 py = *reinterpret_cast<const float4*>(pyl + h * S + lq * 4);
        float4 o;
        o.x = px * py.x; o.y = px * py.y; o.z = px * py.z; o.w = px * py.w;
        *reinterpret_cast<float4*>(probs + h * N2 + k * S + lq * 4) = o;
    }
}

// ---------------------------------------------------------------------------
// 4) Stage 1: T[b,h,i,l,c] = sum_k px[h,i,k] * hs[b,c,l,k]
//    grid 384 (b,l), 256 threads. Per-thread x row (48 floats) lives in
//    REGISTERS (h-invariant); only px tile in smem (broadcast reads).
// ---------------------------------------------------------------------------
__global__ void __launch_bounds__(256, 3) k_stage1(const float* __restrict__ hs) {
    __shared__ __align__(16) float pxs[S * S];
    int b = blockIdx.x / S;
    int l = blockIdx.x - b * S;
    int tid = threadIdx.x;

    // load x[c=tid, l, 0..47] into registers (contiguous, 16B aligned)
    const float* src = hs + (size_t)b * (CH * S * S) + (size_t)tid * (S * S) + l * S;
    float xf[48];
    #pragma unroll
    for (int q = 0; q < 12; ++q) {
        float4 v = *reinterpret_cast<const float4*>(src + 4 * q);
        xf[4 * q] = v.x; xf[4 * q + 1] = v.y; xf[4 * q + 2] = v.z; xf[4 * q + 3] = v.w;
    }
    ull xp[24];
    #pragma unroll
    for (int m = 0; m < 24; ++m) xp[m] = pack2(xf[2 * m], xf[2 * m + 1]);

    for (int h = 0; h < NH; ++h) {
        __syncthreads();
        for (int idx = tid; idx < S * S; idx += 256) pxs[idx] = g_px[h * (S * S) + idx];
        __syncthreads();
        float* Tb = g_T + ((size_t)((b * NH + h) * S) * S + l) * CH + tid;
        for (int i0 = 0; i0 < S; i0 += 8) {
            ull acc[8];
            #pragma unroll
            for (int ii = 0; ii < 8; ++ii) acc[ii] = 0ull;
            #pragma unroll
            for (int k4 = 0; k4 < 12; ++k4) {
                #pragma unroll
                for (int ii = 0; ii < 8; ++ii) {
                    ulonglong2 p = reinterpret_cast<const ulonglong2*>(pxs + (i0 + ii) * S)[k4];
                    fma2(acc[ii], p.x, xp[2 * k4]);
                    fma2(acc[ii], p.y, xp[2 * k4 + 1]);
                }
            }
            #pragma unroll
            for (int ii = 0; ii < 8; ++ii) {
                float lo, hi;
                unpack2(acc[ii], lo, hi);
                Tb[(size_t)(i0 + ii) * (S * CH)] = lo + hi;
            }
        }
    }
}

// ---------------------------------------------------------------------------
// 5) Stage 2: vals[m=(b,j,i), q=(h,c)] = sum_l py[h,j,l] * T[b,h,i,l,c]
//    grid 384 (b,i), 256 threads. Per-thread T column (48 floats, per h)
//    loaded straight to REGISTERS via coalesced LDG.32; py in smem broadcast.
//    Writes fp16 directly (feeds HMMA GEMM).
// ---------------------------------------------------------------------------
__global__ void __launch_bounds__(256, 3) k_stage2() {
    __shared__ __align__(16) float pys[S * S];
    int b = blockIdx.x / S;
    int i = blockIdx.x - b * S;
    int tid = threadIdx.x;

    for (int h = 0; h < NH; ++h) {
        __syncthreads();
        for (int idx = tid; idx < S * S; idx += 256) pys[idx] = g_py[h * (S * S) + idx];
        __syncthreads();

        // T[b,h,i,l,c=tid], l stride CH -> warp-coalesced LDG.32
        const float* Tsrc = g_T + (size_t)((b * NH + h) * S + i) * (S * CH) + tid;
        float tf[48];
        #pragma unroll
        for (int l = 0; l < S; ++l) tf[l] = Tsrc[(size_t)l * CH];
        ull tp[24];
        #pragma unroll
        for (int m = 0; m < 24; ++m) tp[m] = pack2(tf[2 * m], tf[2 * m + 1]);

        size_t vb = (size_t)(b * N2 + i) * N2 + h * CH + tid;
        for (int j0 = 0; j0 < S; j0 += 8) {
            ull acc[8];
            #pragma unroll
            for (int jj = 0; jj < 8; ++jj) acc[jj] = 0ull;
            #pragma unroll
            for (int l4 = 0; l4 < 12; ++l4) {
                #pragma unroll
                for (int jj = 0; jj < 8; ++jj) {
                    ulonglong2 p = reinterpret_cast<const ulonglong2*>(pys + (j0 + jj) * S)[l4];
                    fma2(acc[jj], p.x, tp[2 * l4]);
                    fma2(acc[jj], p.y, tp[2 * l4 + 1]);
                }
            }
            #pragma unroll
            for (int jj = 0; jj < 8; ++jj) {
                float lo, hi;
                unpack2(acc[jj], lo, hi);
                g_Af[vb + (size_t)(j0 + jj) * (S * N2)] = __float2half_rn(lo + hi);
            }
        }
    }
}

// ---------------------------------------------------------------------------
// 6) HMMA GEMM: out[m][o] = (sum_q A[m][q]*W256[o][q])/256 + bias[o]
//    BM=128, BN=128, BK=32, 72 stages, 3-buffer cp.async, ldmatrix loads.
//    fp16 split-B: D += A*Bhi + A*Blo   (A single fp16)
//    SMEM rows: 64 B data + 16 pad (stride 80) -> conflict-free LDSM.
// ---------------------------------------------------------------------------
#define GS_STRIDE 80
#define ARR_BYTES (128 * GS_STRIDE)      // 10240
#define STAGE_BYTES (3 * ARR_BYTES)      // 30720  (A, Bhi, Blo)
#define KSTEPS 72                        // 2304 / 32
#define SMEM_GEMM (3 * STAGE_BYTES)      // 92160

#define GISSUE(s_) do { \
    uint32_t d_ = pd + ((s_) % 3) * STAGE_BYTES; \
    size_t ko_ = (size_t)(s_) * 64; \
    CP_ASYNC16(d_,                      gA  + ko_); \
    CP_ASYNC16(d_ + 16,                 gA  + ko_ + 16); \
    CP_ASYNC16(d_ + ARR_BYTES,          gBh + ko_); \
    CP_ASYNC16(d_ + ARR_BYTES + 16,     gBh + ko_ + 16); \
    CP_ASYNC16(d_ + 2 * ARR_BYTES,      gBl + ko_); \
    CP_ASYNC16(d_ + 2 * ARR_BYTES + 16, gBl + ko_ + 16); \
    CP_COMMIT(); \
} while (0)

__global__ void __launch_bounds__(256) k_gemm_mma(const float* __restrict__ bias,
                                                  float* __restrict__ out) {
    extern __shared__ __align__(16) char gsm[];
    uint32_t sb = smem_u32(gsm);
    int tid = threadIdx.x;
    int wid = tid >> 5;
    int lane = tid & 31;
    int gq = lane >> 2;
    int tc = lane & 3;
    int n0 = blockIdx.x * 128;
    int m0 = blockIdx.y * 128;
    int wm = (wid >> 1) * 32;
    int wn = (wid & 1) * 64;

    float c[2][8][4];
    #pragma unroll
    for (int mi = 0; mi < 2; ++mi)
        #pragma unroll
        for (int ni = 0; ni < 8; ++ni)
            #pragma unroll
            for (int r4 = 0; r4 < 4; ++r4) c[mi][ni][r4] = 0.f;

    // producer: thread -> row (tid>>1), 32B half (tid&1)
    int pr = tid >> 1;
    int ph = tid & 1;
    const char* gA  = (const char*)g_Af + ((size_t)(m0 + pr) * N2) * 2 + ph * 32;
    const char* gBh = (const char*)g_Bh + ((size_t)(n0 + pr) * N2) * 2 + ph * 32;
    const char* gBl = (const char*)g_Bl + ((size_t)(n0 + pr) * N2) * 2 + ph * 32;
    uint32_t pd = sb + pr * GS_STRIDE + ph * 32;

    // ldmatrix lane roles
    int arow = (lane & 7) + ((lane >> 3) & 1) * 8;   // row within m16 tile
    int achk = lane >> 4;                            // k8 chunk within k16
    int brow = lane & 7;
    int bchk = (lane >> 3) & 1;

    GISSUE(0);
    GISSUE(1);

    for (int s = 0; s < KSTEPS; ++s) {
        if (s) __syncthreads();                       // stage s-1 consumers done
        if (s + 2 < KSTEPS) {
            GISSUE(s + 2);
            asm volatile("cp.async.wait_group 2;" ::: "memory");
        } else if (s == KSTEPS - 2) {
            asm volatile("cp.async.wait_group 1;" ::: "memory");
        } else {
            asm volatile("cp.async.wait_group 0;" ::: "memory");
        }
        __syncthreads();

        uint32_t st = sb + (s % 3) * STAGE_BYTES;
        #pragma unroll
        for (int ks = 0; ks < 2; ++ks) {
            uint32_t a[2][4];
            #pragma unroll
            for (int mi = 0; mi < 2; ++mi) {
                uint32_t aaddr = st + (wm + mi * 16 + arow) * GS_STRIDE + (ks * 2 + achk) * 16;
                LDSM4(a[mi][0], a[mi][1], a[mi][2], a[mi][3], aaddr);
            }
            #pragma unroll
            for (int nt = 0; nt < 8; ++nt) {
                uint32_t baddr = st + ARR_BYTES + (wn + nt * 8 + brow) * GS_STRIDE
                               + (ks * 2 + bchk) * 16;
                uint32_t bh0, bh1, bl0, bl1;
                LDSM2(bh0, bh1, baddr);
                LDSM2(bl0, bl1, baddr + ARR_BYTES);
                #pragma unroll
                for (int mi = 0; mi < 2; ++mi) {
                    MMA16816H(c[mi][nt], a[mi], bh0, bh1);
                    MMA16816H(c[mi][nt], a[mi], bl0, bl1);
                }
            }
        }
    }

    // epilogue: out[b*CH*N2 + o*N2 + mrel], m contiguous; undo x256 W scale
    const float inv = 1.0f / 256.0f;
    int by = blockIdx.y;
    int b = by / 18;
    int mrel0 = (by - b * 18) * 128;
    float* ob = out + (size_t)b * (CH * N2) + mrel0;
    #pragma unroll
    for (int ni = 0; ni < 8; ++ni) {
        int o = n0 + wn + ni * 8 + tc * 2;
        float bv0 = __ldg(bias + o);
        float bv1 = __ldg(bias + o + 1);
        #pragma unroll
        for (int mi = 0; mi < 2; ++mi) {
            int m = wm + mi * 16 + gq;
            ob[(size_t)o * N2 + m]           = c[mi][ni][0] * inv + bv0;
            ob[(size_t)(o + 1) * N2 + m]     = c[mi][ni][1] * inv + bv1;
            ob[(size_t)o * N2 + m + 8]       = c[mi][ni][2] * inv + bv0;
            ob[(size_t)(o + 1) * N2 + m + 8] = c[mi][ni][3] * inv + bv1;
        }
    }
}

// ---------------------------------------------------------------------------
extern "C" void kernel_launch(void* const* d_in, const int* in_sizes, int n_in,
                              void* d_out, int out_size) {
    const float* hs      = (const float*)d_in[0];
    const float* centers = (const float*)d_in[1];
    const float* spreads = (const float*)d_in[2];
    const float* vw      = (const float*)d_in[3];
    const float* vb      = (const float*)d_in[4];
    float* out = (float*)d_out;

    cudaFuncSetAttribute(k_gemm_mma, cudaFuncAttributeMaxDynamicSharedMemorySize, SMEM_GEMM);

    k_axes<<<1, 864>>>(centers, spreads);
    k_wconv<<<2304, 256>>>(vw);
    k_probs<<<2304, 256>>>(out);
    k_stage1<<<384, 256>>>(hs);
    k_stage2<<<384, 256>>>();
    k_gemm_mma<<<dim3(2, 144), 256, SMEM_GEMM>>>(vb, out);
}